// round 16
// baseline (speedup 1.0000x reference)
#include <cuda_runtime.h>
#include <cuda_bf16.h>
#include <cstdint>

// VSC3x3Rulebook on GB300 — HMMA bf16-split + TMA bulk-reduce scatter.
// r15 pipeline (4 warp-pair pipelines, named barriers, truncation A-split,
// all-register W, sequential s-tiles) + double-buffered D stage with
// wait_group.read 1 (reduce read-latency overlaps a full tile).
//   out = scatter_add_{k,m}( feats[in_rows[k,m]] @ weight[k] -> out_rows[k,m] ) + bias
//   d_out (float32): [ float(coords) | out[N,64] ]

#define TILE_E 128
#define GRID_X 32

// dynamic smem layout (16B aligned base)
#define AHI_OFF 0              // 128 x 144B : bf16 A_hi
#define ALO_OFF 18432          // 128 x 144B : bf16 A_lo
#define STG_OFF(b) (36864 + (b) * 36864)   // 2 x (128 x 288B) f32 D stage
#define SMEM_SZ 110592

// ---- merged prep: bias-init of out + coords int->float cast ----
__global__ void vsc_prep(float4* __restrict__ out4,
                         const float4* __restrict__ bias4, int total4,
                         const int4* __restrict__ coords4,
                         float4* __restrict__ outc4, int nc4) {
    int idx = blockIdx.x * blockDim.x + threadIdx.x;
    if (idx < total4) {
        out4[idx] = bias4[idx & 15];
    } else {
        int j = idx - total4;
        if (j < nc4) {
            int4 v = coords4[j];
            outc4[j] = make_float4((float)v.x, (float)v.y, (float)v.z, (float)v.w);
        }
    }
}

// Truncation split: hi = a with low 16 bits cleared (exact bf16),
// lo = rn_bf16(a - hi). r.x packs {hi(b),hi(a)}, r.y packs {lo(b),lo(a)}.
__device__ __forceinline__ uint2 bf16split2(float a, float b) {
    const uint32_t ua = __float_as_uint(a), ub = __float_as_uint(b);
    uint2 r;
    asm("prmt.b32 %0, %1, %2, 0x7632;" : "=r"(r.x) : "r"(ua), "r"(ub));
    const float ha = __uint_as_float(ua & 0xFFFF0000u);
    const float hb = __uint_as_float(ub & 0xFFFF0000u);
    const float la = a - ha, lb = b - hb;
    asm("cvt.rn.bf16x2.f32 %0, %1, %2;" : "=r"(r.y) : "f"(lb), "f"(la));
    return r;
}

__device__ __forceinline__ void mma16816(float* c, const uint32_t* a,
                                         uint32_t b0, uint32_t b1) {
    asm volatile(
        "mma.sync.aligned.m16n8k16.row.col.f32.bf16.bf16.f32 "
        "{%0,%1,%2,%3}, {%4,%5,%6,%7}, {%8,%9}, {%0,%1,%2,%3};"
        : "+f"(c[0]), "+f"(c[1]), "+f"(c[2]), "+f"(c[3])
        : "r"(a[0]), "r"(a[1]), "r"(a[2]), "r"(a[3]), "r"(b0), "r"(b1));
}

#define LDMX4(r, addr)                                                     \
    asm volatile("ldmatrix.sync.aligned.m8n8.x4.shared.b16 "               \
                 "{%0,%1,%2,%3}, [%4];"                                    \
                 : "=r"((r)[0]), "=r"((r)[1]), "=r"((r)[2]), "=r"((r)[3])  \
                 : "r"(addr))

#define PAIR_BAR(id)                                                       \
    asm volatile("bar.sync %0, 64;" :: "r"(id) : "memory")

__global__ __launch_bounds__(256, 2) void vsc_mma(
    const float* __restrict__ feats,
    const int*   __restrict__ in_rows,
    const int*   __restrict__ out_rows,
    const float* __restrict__ weight,
    float*       __restrict__ out,
    int M, int ntiles)
{
    extern __shared__ __align__(16) char smem[];
    const uint32_t sb = (uint32_t)__cvta_generic_to_shared(smem);

    const int tid   = threadIdx.x;
    const int w     = tid >> 5;
    const int l     = tid & 31;
    const int eslab = w >> 1;    // 0..3 : 32-entry slab (pair id)
    const int nhalf = w & 1;     // 0/1  : output-column half
    const int k     = blockIdx.y;
    const long kM   = (long)k * M;
    const float* Wg = weight + (size_t)k * 4096;   // [ci][co]

    // ---- W_hi AND W_lo fragments -> registers (64 regs) ----
    uint32_t Bhi[4][4][2], Blo[4][4][2];
    {
        const int n = nhalf * 32 + (l >> 2);
        #pragma unroll
        for (int nt = 0; nt < 4; nt++)
            #pragma unroll
            for (int ks = 0; ks < 4; ks++)
                #pragma unroll
                for (int j = 0; j < 2; j++) {
                    const int ci0 = ks * 16 + j * 8 + 2 * (l & 3);
                    const float w0 = Wg[(size_t)ci0 * 64 + n + nt * 8];
                    const float w1 = Wg[(size_t)(ci0 + 1) * 64 + n + nt * 8];
                    const __nv_bfloat16 h0 = __float2bfloat16(w0);
                    const __nv_bfloat16 h1 = __float2bfloat16(w1);
                    Bhi[nt][ks][j] =
                        (uint32_t)__bfloat16_as_ushort(h0)
                      | ((uint32_t)__bfloat16_as_ushort(h1) << 16);
                    const float l0 = w0 - __bfloat162float(h0);
                    const float l1 = w1 - __bfloat162float(h1);
                    Blo[nt][ks][j] =
                        (uint32_t)__bfloat16_as_ushort(__float2bfloat16(l0))
                      | ((uint32_t)__bfloat16_as_ushort(__float2bfloat16(l1)) << 16);
                }
    }

    const uint32_t a_row = (l & 7) + ((l >> 3) & 1) * 8;
    const uint32_t a_kof = (l >> 4) * 8;

    // pair-local gather striping: 64 threads cover 32 entries x 8 octets
    const int pt  = (nhalf << 5) | l;   // 0..63 within pair
    const int er2 = pt >> 3;            // 0..7
    const int g8  = pt & 7;             // ci octet
    const int bar = eslab + 1;          // named barrier id 1..4

    int buf = 0;   // D-stage buffer parity
    for (int tile = blockIdx.x; tile < ntiles; tile += GRID_X) {
        const int ebase = tile * TILE_E;

        // each warp of the pair owns 16 reduce entries (lanes 0..15)
        int orw = -1;
        if (l < 16) {
            const int eg = ebase + eslab * 32 + nhalf * 16 + l;
            if (eg < M) orw = __ldg(out_rows + kM + eg);
        }

        // ---- gather + split + STS (own slab rows only) ----
        #pragma unroll
        for (int p = 0; p < 4; p++) {
            const int e = eslab * 32 + p * 8 + er2;
            int eg = ebase + e;
            if (eg >= M) eg = M - 1;
            const int irow = __ldg(in_rows + kM + eg);
            const float4* fp = reinterpret_cast<const float4*>(
                feats + (size_t)irow * 64 + g8 * 8);
            const float4 v0 = __ldg(fp);
            const float4 v1 = __ldg(fp + 1);
            const uint2 p0 = bf16split2(v0.x, v0.y);
            const uint2 p1 = bf16split2(v0.z, v0.w);
            const uint2 p2 = bf16split2(v1.x, v1.y);
            const uint2 p3 = bf16split2(v1.z, v1.w);
            const int off = e * 144 + g8 * 16;
            *reinterpret_cast<uint4*>(smem + AHI_OFF + off) =
                make_uint4(p0.x, p1.x, p2.x, p3.x);
            *reinterpret_cast<uint4*>(smem + ALO_OFF + off) =
                make_uint4(p0.y, p1.y, p2.y, p3.y);
        }
        PAIR_BAR(bar);   // slab's A rows ready for both warps of the pair

        float acc[4][4];
        float* stg = reinterpret_cast<float*>(smem + STG_OFF(buf));
        const int r0 = l >> 2;            // 0..7
        const int cb = 2 * (l & 3);       // 0,2,4,6

        // ---- compute s = 0 (rows eslab*32 .. +15) ----
        #pragma unroll
        for (int nt = 0; nt < 4; nt++)
            #pragma unroll
            for (int r = 0; r < 4; r++) acc[nt][r] = 0.f;
        #pragma unroll
        for (int ks = 0; ks < 4; ks++) {
            const uint32_t ao =
                (eslab * 32 + a_row) * 144 + (ks * 16 + a_kof) * 2;
            uint32_t ahi[4], alo[4];
            LDMX4(ahi, sb + AHI_OFF + ao);
            LDMX4(alo, sb + ALO_OFF + ao);
            #pragma unroll
            for (int nt = 0; nt < 4; nt++) {
                mma16816(acc[nt], ahi, Bhi[nt][ks][0], Bhi[nt][ks][1]);
                mma16816(acc[nt], ahi, Blo[nt][ks][0], Blo[nt][ks][1]);
                mma16816(acc[nt], alo, Bhi[nt][ks][0], Bhi[nt][ks][1]);
            }
        }

        // the reduce group that last READ stage buffer `buf` was committed
        // two tiles ago; allow the most recent group (tile t-1, other buffer)
        // to still be in flight.
        asm volatile("cp.async.bulk.wait_group.read 1;" ::: "memory");
        PAIR_BAR(bar);   // partner's wait done too -> buffer free pair-wide

        // ---- stage s = 0 ----
        {
            const int eb = eslab * 32;
            #pragma unroll
            for (int nt = 0; nt < 4; nt++) {
                const int c = nhalf * 32 + nt * 8 + cb;
                *reinterpret_cast<float2*>(&stg[(eb + r0) * 72 + c]) =
                    make_float2(acc[nt][0], acc[nt][1]);
                *reinterpret_cast<float2*>(&stg[(eb + r0 + 8) * 72 + c]) =
                    make_float2(acc[nt][2], acc[nt][3]);
            }
        }

        // ---- compute s = 1 (rows eslab*32+16 .. +31), reuse acc ----
        #pragma unroll
        for (int nt = 0; nt < 4; nt++)
            #pragma unroll
            for (int r = 0; r < 4; r++) acc[nt][r] = 0.f;
        #pragma unroll
        for (int ks = 0; ks < 4; ks++) {
            const uint32_t ao =
                (eslab * 32 + 16 + a_row) * 144 + (ks * 16 + a_kof) * 2;
            uint32_t ahi[4], alo[4];
            LDMX4(ahi, sb + AHI_OFF + ao);
            LDMX4(alo, sb + ALO_OFF + ao);
            #pragma unroll
            for (int nt = 0; nt < 4; nt++) {
                mma16816(acc[nt], ahi, Bhi[nt][ks][0], Bhi[nt][ks][1]);
                mma16816(acc[nt], ahi, Blo[nt][ks][0], Blo[nt][ks][1]);
                mma16816(acc[nt], alo, Bhi[nt][ks][0], Bhi[nt][ks][1]);
            }
        }

        // ---- stage s = 1 ----
        {
            const int eb = eslab * 32 + 16;
            #pragma unroll
            for (int nt = 0; nt < 4; nt++) {
                const int c = nhalf * 32 + nt * 8 + cb;
                *reinterpret_cast<float2*>(&stg[(eb + r0) * 72 + c]) =
                    make_float2(acc[nt][0], acc[nt][1]);
                *reinterpret_cast<float2*>(&stg[(eb + r0 + 8) * 72 + c]) =
                    make_float2(acc[nt][2], acc[nt][3]);
            }
        }
        asm volatile("fence.proxy.async.shared::cta;" ::: "memory");
        PAIR_BAR(bar);   // all stage writes + all ldmatrix of this tile done

        if (orw >= 0) {
            const int e = eslab * 32 + nhalf * 16 + l;
            const float* dst = out + (size_t)orw * 64;
            const uint32_t src = sb + STG_OFF(buf) + e * 288;
            asm volatile(
                "cp.reduce.async.bulk.global.shared::cta.bulk_group.add.f32 "
                "[%0], [%1], 256;"
                :: "l"(dst), "r"(src) : "memory");
        }
        asm volatile("cp.async.bulk.commit_group;" ::: "memory");
        // next gather overwrites this slab's A rows: safe, all warps are past
        // the last pair barrier (and thus past all ldmatrix reads of tile t).

        buf ^= 1;
    }

    asm volatile("cp.async.bulk.wait_group 0;" ::: "memory");
}

extern "C" void kernel_launch(void* const* d_in, const int* in_sizes, int n_in,
                              void* d_out, int out_size) {
    const int*   coords   = (const int*)  d_in[0];
    const float* feats    = (const float*)d_in[1];
    const int*   in_rows  = (const int*)  d_in[2];
    const int*   out_rows = (const int*)  d_in[3];
    const float* weight   = (const float*)d_in[4];
    const float* bias     = (const float*)d_in[5];

    const int N = in_sizes[1] / 64;   // feats is [N, 64]
    const int M = in_sizes[2] / 9;    // in_rows is [9, M]

    // d_out is float32: [ float(coords) | out[N,64] ]
    float* outf = (float*)d_out;
    long coords_elems = (long)out_size - (long)N * 64;
    if (coords_elems < 0) coords_elems = 0;
    if (coords_elems > in_sizes[0]) coords_elems = in_sizes[0];
    float* out = outf + coords_elems;

    const int total4 = N * 16;                    // out floats / 4
    const int nc4    = (int)(coords_elems / 4);   // coords: N*3 divisible by 4
    const int tot    = total4 + nc4;
    vsc_prep<<<(tot + 255) / 256, 256>>>(
        (float4*)out, (const float4*)bias, total4,
        (const int4*)coords, (float4*)outf, nc4);

    cudaFuncSetAttribute(vsc_mma, cudaFuncAttributeMaxDynamicSharedMemorySize,
                         SMEM_SZ);
    const int ntiles = (M + TILE_E - 1) / TILE_E;
    dim3 grid(GRID_X, 9);
    vsc_mma<<<grid, 256, SMEM_SZ>>>(feats, in_rows, out_rows, weight, out,
                                    M, ntiles);
}

// round 17
// speedup vs baseline: 1.0711x; 1.0711x over previous
#include <cuda_runtime.h>
#include <cuda_bf16.h>
#include <cstdint>

// VSC3x3Rulebook on GB300 — HMMA bf16-split + TMA bulk-reduce scatter.
// r15 pipeline (4 warp-pair pipelines, named barriers, truncation A-split,
// all-register W, sequential s-tiles, single D stage + wait_group.read 0)
// with a flattened (k,tile) grid: 296 CTAs in contiguous balanced chunks so
// every SM carries exactly 2 CTAs.
//   out = scatter_add_{k,m}( feats[in_rows[k,m]] @ weight[k] -> out_rows[k,m] ) + bias
//   d_out (float32): [ float(coords) | out[N,64] ]

#define TILE_E 128
#define NBLK   296

// dynamic smem layout (16B aligned base)
#define AHI_OFF 0          // 128 x 144B : bf16 A_hi
#define ALO_OFF 18432      // 128 x 144B : bf16 A_lo
#define STG_OFF 36864      // 128 x 288B : f32 D stage (72-float stride)
#define SMEM_SZ 73728

// ---- merged prep: bias-init of out + coords int->float cast ----
__global__ void vsc_prep(float4* __restrict__ out4,
                         const float4* __restrict__ bias4, int total4,
                         const int4* __restrict__ coords4,
                         float4* __restrict__ outc4, int nc4) {
    int idx = blockIdx.x * blockDim.x + threadIdx.x;
    if (idx < total4) {
        out4[idx] = bias4[idx & 15];
    } else {
        int j = idx - total4;
        if (j < nc4) {
            int4 v = coords4[j];
            outc4[j] = make_float4((float)v.x, (float)v.y, (float)v.z, (float)v.w);
        }
    }
}

// Truncation split: hi = a with low 16 bits cleared (exact bf16),
// lo = rn_bf16(a - hi). r.x packs {hi(b),hi(a)}, r.y packs {lo(b),lo(a)}.
__device__ __forceinline__ uint2 bf16split2(float a, float b) {
    const uint32_t ua = __float_as_uint(a), ub = __float_as_uint(b);
    uint2 r;
    asm("prmt.b32 %0, %1, %2, 0x7632;" : "=r"(r.x) : "r"(ua), "r"(ub));
    const float ha = __uint_as_float(ua & 0xFFFF0000u);
    const float hb = __uint_as_float(ub & 0xFFFF0000u);
    const float la = a - ha, lb = b - hb;
    asm("cvt.rn.bf16x2.f32 %0, %1, %2;" : "=r"(r.y) : "f"(lb), "f"(la));
    return r;
}

__device__ __forceinline__ void mma16816(float* c, const uint32_t* a,
                                         uint32_t b0, uint32_t b1) {
    asm volatile(
        "mma.sync.aligned.m16n8k16.row.col.f32.bf16.bf16.f32 "
        "{%0,%1,%2,%3}, {%4,%5,%6,%7}, {%8,%9}, {%0,%1,%2,%3};"
        : "+f"(c[0]), "+f"(c[1]), "+f"(c[2]), "+f"(c[3])
        : "r"(a[0]), "r"(a[1]), "r"(a[2]), "r"(a[3]), "r"(b0), "r"(b1));
}

#define LDMX4(r, addr)                                                     \
    asm volatile("ldmatrix.sync.aligned.m8n8.x4.shared.b16 "               \
                 "{%0,%1,%2,%3}, [%4];"                                    \
                 : "=r"((r)[0]), "=r"((r)[1]), "=r"((r)[2]), "=r"((r)[3])  \
                 : "r"(addr))

#define PAIR_BAR(id)                                                       \
    asm volatile("bar.sync %0, 64;" :: "r"(id) : "memory")

__global__ __launch_bounds__(256, 2) void vsc_mma(
    const float* __restrict__ feats,
    const int*   __restrict__ in_rows,
    const int*   __restrict__ out_rows,
    const float* __restrict__ weight,
    float*       __restrict__ out,
    int M, int ntiles)
{
    extern __shared__ __align__(16) char smem[];
    const uint32_t sb = (uint32_t)__cvta_generic_to_shared(smem);

    const int tid   = threadIdx.x;
    const int w     = tid >> 5;
    const int l     = tid & 31;
    const int eslab = w >> 1;    // 0..3 : 32-entry slab (pair id)
    const int nhalf = w & 1;     // 0/1  : output-column half

    const uint32_t a_row = (l & 7) + ((l >> 3) & 1) * 8;
    const uint32_t a_kof = (l >> 4) * 8;

    // pair-local gather striping: 64 threads cover 32 entries x 8 octets
    const int pt  = (nhalf << 5) | l;   // 0..63 within pair
    const int er2 = pt >> 3;            // 0..7
    const int g8  = pt & 7;             // ci octet
    const int bar = eslab + 1;          // named barrier id 1..4

    // balanced contiguous chunk of flattened (k,tile) units
    const int total = 9 * ntiles;
    int u          = (int)(((long)total * blockIdx.x) / gridDim.x);
    const int uend = (int)(((long)total * (blockIdx.x + 1)) / gridDim.x);

    uint32_t Bhi[4][4][2], Blo[4][4][2];

    while (u < uend) {
        const int kk = u / ntiles;
        const int kchunk_end = min(uend, (kk + 1) * ntiles);
        const long kM = (long)kk * M;
        const float* Wg = weight + (size_t)kk * 4096;   // [ci][co]

        // ---- W_hi AND W_lo fragments -> registers (64 regs) ----
        {
            const int n = nhalf * 32 + (l >> 2);
            #pragma unroll
            for (int nt = 0; nt < 4; nt++)
                #pragma unroll
                for (int ks = 0; ks < 4; ks++)
                    #pragma unroll
                    for (int j = 0; j < 2; j++) {
                        const int ci0 = ks * 16 + j * 8 + 2 * (l & 3);
                        const float w0 = Wg[(size_t)ci0 * 64 + n + nt * 8];
                        const float w1 = Wg[(size_t)(ci0 + 1) * 64 + n + nt * 8];
                        const __nv_bfloat16 h0 = __float2bfloat16(w0);
                        const __nv_bfloat16 h1 = __float2bfloat16(w1);
                        Bhi[nt][ks][j] =
                            (uint32_t)__bfloat16_as_ushort(h0)
                          | ((uint32_t)__bfloat16_as_ushort(h1) << 16);
                        const float l0 = w0 - __bfloat162float(h0);
                        const float l1 = w1 - __bfloat162float(h1);
                        Blo[nt][ks][j] =
                            (uint32_t)__bfloat16_as_ushort(__float2bfloat16(l0))
                          | ((uint32_t)__bfloat16_as_ushort(__float2bfloat16(l1)) << 16);
                    }
        }

        for (; u < kchunk_end; u++) {
            const int tile  = u - kk * ntiles;
            const int ebase = tile * TILE_E;

            // each warp of the pair owns 16 reduce entries (lanes 0..15)
            int orw = -1;
            if (l < 16) {
                const int eg = ebase + eslab * 32 + nhalf * 16 + l;
                if (eg < M) orw = __ldg(out_rows + kM + eg);
            }

            // ---- gather + split + STS (own slab rows only) ----
            #pragma unroll
            for (int p = 0; p < 4; p++) {
                const int e = eslab * 32 + p * 8 + er2;
                int eg = ebase + e;
                if (eg >= M) eg = M - 1;
                const int irow = __ldg(in_rows + kM + eg);
                const float4* fp = reinterpret_cast<const float4*>(
                    feats + (size_t)irow * 64 + g8 * 8);
                const float4 v0 = __ldg(fp);
                const float4 v1 = __ldg(fp + 1);
                const uint2 p0 = bf16split2(v0.x, v0.y);
                const uint2 p1 = bf16split2(v0.z, v0.w);
                const uint2 p2 = bf16split2(v1.x, v1.y);
                const uint2 p3 = bf16split2(v1.z, v1.w);
                const int off = e * 144 + g8 * 16;
                *reinterpret_cast<uint4*>(smem + AHI_OFF + off) =
                    make_uint4(p0.x, p1.x, p2.x, p3.x);
                *reinterpret_cast<uint4*>(smem + ALO_OFF + off) =
                    make_uint4(p0.y, p1.y, p2.y, p3.y);
            }
            PAIR_BAR(bar);   // slab's A rows ready for both warps of the pair

            float acc[4][4];
            float* stg = reinterpret_cast<float*>(smem + STG_OFF);
            const int r0 = l >> 2;            // 0..7
            const int cb = 2 * (l & 3);       // 0,2,4,6

            // ---- compute s = 0 (rows eslab*32 .. +15) ----
            #pragma unroll
            for (int nt = 0; nt < 4; nt++)
                #pragma unroll
                for (int r = 0; r < 4; r++) acc[nt][r] = 0.f;
            #pragma unroll
            for (int ks = 0; ks < 4; ks++) {
                const uint32_t ao =
                    (eslab * 32 + a_row) * 144 + (ks * 16 + a_kof) * 2;
                uint32_t ahi[4], alo[4];
                LDMX4(ahi, sb + AHI_OFF + ao);
                LDMX4(alo, sb + ALO_OFF + ao);
                #pragma unroll
                for (int nt = 0; nt < 4; nt++) {
                    mma16816(acc[nt], ahi, Bhi[nt][ks][0], Bhi[nt][ks][1]);
                    mma16816(acc[nt], ahi, Blo[nt][ks][0], Blo[nt][ks][1]);
                    mma16816(acc[nt], alo, Bhi[nt][ks][0], Bhi[nt][ks][1]);
                }
            }

            // previous reduce groups must have READ the slab's stage rows
            asm volatile("cp.async.bulk.wait_group.read 0;" ::: "memory");
            PAIR_BAR(bar);   // stage rows free for both warps

            // ---- stage s = 0 ----
            {
                const int eb = eslab * 32;
                #pragma unroll
                for (int nt = 0; nt < 4; nt++) {
                    const int c = nhalf * 32 + nt * 8 + cb;
                    *reinterpret_cast<float2*>(&stg[(eb + r0) * 72 + c]) =
                        make_float2(acc[nt][0], acc[nt][1]);
                    *reinterpret_cast<float2*>(&stg[(eb + r0 + 8) * 72 + c]) =
                        make_float2(acc[nt][2], acc[nt][3]);
                }
            }

            // ---- compute s = 1 (rows eslab*32+16 .. +31), reuse acc ----
            #pragma unroll
            for (int nt = 0; nt < 4; nt++)
                #pragma unroll
                for (int r = 0; r < 4; r++) acc[nt][r] = 0.f;
            #pragma unroll
            for (int ks = 0; ks < 4; ks++) {
                const uint32_t ao =
                    (eslab * 32 + 16 + a_row) * 144 + (ks * 16 + a_kof) * 2;
                uint32_t ahi[4], alo[4];
                LDMX4(ahi, sb + AHI_OFF + ao);
                LDMX4(alo, sb + ALO_OFF + ao);
                #pragma unroll
                for (int nt = 0; nt < 4; nt++) {
                    mma16816(acc[nt], ahi, Bhi[nt][ks][0], Bhi[nt][ks][1]);
                    mma16816(acc[nt], ahi, Blo[nt][ks][0], Blo[nt][ks][1]);
                    mma16816(acc[nt], alo, Bhi[nt][ks][0], Bhi[nt][ks][1]);
                }
            }

            // ---- stage s = 1 ----
            {
                const int eb = eslab * 32 + 16;
                #pragma unroll
                for (int nt = 0; nt < 4; nt++) {
                    const int c = nhalf * 32 + nt * 8 + cb;
                    *reinterpret_cast<float2*>(&stg[(eb + r0) * 72 + c]) =
                        make_float2(acc[nt][0], acc[nt][1]);
                    *reinterpret_cast<float2*>(&stg[(eb + r0 + 8) * 72 + c]) =
                        make_float2(acc[nt][2], acc[nt][3]);
                }
            }
            asm volatile("fence.proxy.async.shared::cta;" ::: "memory");
            PAIR_BAR(bar);   // all stage writes + all ldmatrix of tile done

            if (orw >= 0) {
                const int e = eslab * 32 + nhalf * 16 + l;
                const float* dst = out + (size_t)orw * 64;
                const uint32_t src = sb + STG_OFF + e * 288;
                asm volatile(
                    "cp.reduce.async.bulk.global.shared::cta.bulk_group.add.f32 "
                    "[%0], [%1], 256;"
                    :: "l"(dst), "r"(src) : "memory");
            }
            asm volatile("cp.async.bulk.commit_group;" ::: "memory");
            // next gather overwrites this slab's A rows: safe, all warps are
            // past the last pair barrier (and thus past all ldmatrix reads).
        }
    }

    asm volatile("cp.async.bulk.wait_group 0;" ::: "memory");
}

extern "C" void kernel_launch(void* const* d_in, const int* in_sizes, int n_in,
                              void* d_out, int out_size) {
    const int*   coords   = (const int*)  d_in[0];
    const float* feats    = (const float*)d_in[1];
    const int*   in_rows  = (const int*)  d_in[2];
    const int*   out_rows = (const int*)  d_in[3];
    const float* weight   = (const float*)d_in[4];
    const float* bias     = (const float*)d_in[5];

    const int N = in_sizes[1] / 64;   // feats is [N, 64]
    const int M = in_sizes[2] / 9;    // in_rows is [9, M]

    // d_out is float32: [ float(coords) | out[N,64] ]
    float* outf = (float*)d_out;
    long coords_elems = (long)out_size - (long)N * 64;
    if (coords_elems < 0) coords_elems = 0;
    if (coords_elems > in_sizes[0]) coords_elems = in_sizes[0];
    float* out = outf + coords_elems;

    const int total4 = N * 16;                    // out floats / 4
    const int nc4    = (int)(coords_elems / 4);   // coords: N*3 divisible by 4
    const int tot    = total4 + nc4;
    vsc_prep<<<(tot + 255) / 256, 256>>>(
        (float4*)out, (const float4*)bias, total4,
        (const int4*)coords, (float4*)outf, nc4);

    cudaFuncSetAttribute(vsc_mma, cudaFuncAttributeMaxDynamicSharedMemorySize,
                         SMEM_SZ);
    const int ntiles = (M + TILE_E - 1) / TILE_E;
    int nblk = NBLK;
    const int total_units = 9 * ntiles;
    if (nblk > total_units) nblk = total_units;
    vsc_mma<<<nblk, 256, SMEM_SZ>>>(feats, in_rows, out_rows, weight, out,
                                    M, ntiles);
}